// round 9
// baseline (speedup 1.0000x reference)
#include <cuda_runtime.h>
#include <math.h>

// Hyp-MLR: N=4096, C=256, D=128, CURV=1
// Single fused kernel: dual GEMM (X.P^T, X.A^T) + stats + approx-asinh
// epilogue. R8: software-pipelined fill — KT=32, 4 phases, next phase's
// gmem loads prefetched into registers before the current FMA block, so
// LDG latency + L1tex wavefront service overlap FMA issue.

#define N_TOT 4096
#define C_TOT 256
#define D_TOT 128
#define BN 64
#define BC 64
#define KT 32
#define STR 68             // k-major row stride in floats (272B, 16B-aligned)
#define TILE_FLOATS (KT * STR)                  // 2176
#define SMEM_FLOATS (3 * TILE_FLOATS + 4 * 256 + 5 * 64)
#define SMEM_BYTES (SMEM_FLOATS * 4)
#define LN2F 0.69314718055994530942f

__device__ __forceinline__ float fast_rcp(float x) {
    float y; asm("rcp.approx.f32 %0, %1;" : "=f"(y) : "f"(x)); return y;
}
__device__ __forceinline__ float fast_sqrt(float x) {
    float y; asm("sqrt.approx.f32 %0, %1;" : "=f"(y) : "f"(x)); return y;
}
__device__ __forceinline__ float fast_lg2(float x) {
    float y; asm("lg2.approx.f32 %0, %1;" : "=f"(y) : "f"(x)); return y;
}
__device__ __forceinline__ float dot4(float4 a, float4 b) {
    return a.x * b.x + a.y * b.y + a.z * b.z + a.w * b.w;
}

__global__ __launch_bounds__(256, 2) void hyp_mlr_kernel(
    const float* __restrict__ X,   // (N, D)
    const float* __restrict__ A,   // (C, D)
    const float* __restrict__ P,   // (C, D)
    float* __restrict__ out)       // (N, C)
{
    extern __shared__ float smem[];
    float* Xs = smem;                       // [KT][STR] k-major
    float* Ps = smem + TILE_FLOATS;
    float* As = smem + 2 * TILE_FLOATS;
    float* sc_x2 = smem + 3 * TILE_FLOATS;  // [4][64] slab partials
    float* sc_p2 = sc_x2 + 256;
    float* sc_a2 = sc_p2 + 256;
    float* sc_pa = sc_a2 + 256;
    float* sx2  = sc_pa + 256;              // [64] finals
    float* sp2  = sx2 + 64;
    float* spa  = sp2 + 64;
    float* sina = spa + 64;
    float* sw2  = sina + 64;

    const int tid = threadIdx.x;
    const int tx  = tid & 15;   // c dim
    const int ty  = tid >> 4;   // n dim
    const int n0  = blockIdx.y * BN;
    const int c0  = blockIdx.x * BC;

    // Fill mapping: warp spans 32 distinct rows at one k -> conflict-free STS.
    const int frow = tid & 63;          // 0..63
    const int fk4  = (tid >> 6) * 2;    // float4-chunk index: 0,2,4,6

    const float* xg = &X[(size_t)(n0 + frow) * D_TOT + fk4 * 4];
    const float* pg = &P[(size_t)(c0 + frow) * D_TOT + fk4 * 4];
    const float* ag = &A[(size_t)(c0 + frow) * D_TOT + fk4 * 4];

    float axp[4][4] = {};   // x.p partials
    float axa[4][4] = {};   // x.a partials
    float x2p = 0.f, p2p = 0.f, a2p = 0.f, pap = 0.f;   // stats partials

    float4 rx[2], rp[2], ra[2];        // register prefetch (one phase)

    // ---- prologue: load + store phase 0
    #pragma unroll
    for (int q = 0; q < 2; q++) {
        rx[q] = *(const float4*)&xg[q * 4];
        rp[q] = *(const float4*)&pg[q * 4];
        ra[q] = *(const float4*)&ag[q * 4];
    }
    #pragma unroll
    for (int q = 0; q < 2; q++) {
        x2p += dot4(rx[q], rx[q]);
        p2p += dot4(rp[q], rp[q]);
        a2p += dot4(ra[q], ra[q]);
        pap += dot4(rp[q], ra[q]);
        int k = (fk4 + q) * 4;
        Xs[(k + 0) * STR + frow] = rx[q].x;
        Xs[(k + 1) * STR + frow] = rx[q].y;
        Xs[(k + 2) * STR + frow] = rx[q].z;
        Xs[(k + 3) * STR + frow] = rx[q].w;
        Ps[(k + 0) * STR + frow] = rp[q].x;
        Ps[(k + 1) * STR + frow] = rp[q].y;
        Ps[(k + 2) * STR + frow] = rp[q].z;
        Ps[(k + 3) * STR + frow] = rp[q].w;
        As[(k + 0) * STR + frow] = ra[q].x;
        As[(k + 1) * STR + frow] = ra[q].y;
        As[(k + 2) * STR + frow] = ra[q].z;
        As[(k + 3) * STR + frow] = ra[q].w;
    }
    __syncthreads();

    #pragma unroll
    for (int ph = 0; ph < 4; ph++) {
        // Prefetch next phase's gmem data (overlaps the FMA block below).
        if (ph < 3) {
            const int kb = (ph + 1) * KT;
            #pragma unroll
            for (int q = 0; q < 2; q++) {
                rx[q] = *(const float4*)&xg[kb + q * 4];
                rp[q] = *(const float4*)&pg[kb + q * 4];
                ra[q] = *(const float4*)&ag[kb + q * 4];
            }
        }

        // FMA block: 32 k, 32 FFMA + 3 LDS.128 per thread per k.
        #pragma unroll 4
        for (int k = 0; k < KT; k++) {
            float4 xv = *(const float4*)&Xs[k * STR + ty * 4];
            float4 pv = *(const float4*)&Ps[k * STR + tx * 4];
            float4 av = *(const float4*)&As[k * STR + tx * 4];
            float xr[4] = {xv.x, xv.y, xv.z, xv.w};
            float pr[4] = {pv.x, pv.y, pv.z, pv.w};
            float ar[4] = {av.x, av.y, av.z, av.w};
            #pragma unroll
            for (int i = 0; i < 4; i++)
                #pragma unroll
                for (int j = 0; j < 4; j++) {
                    axp[i][j] = fmaf(xr[i], pr[j], axp[i][j]);
                    axa[i][j] = fmaf(xr[i], ar[j], axa[i][j]);
                }
        }
        __syncthreads();                 // everyone done reading tile ph

        if (ph < 3) {
            // Stats on in-flight data + conflict-free transposing STS.
            #pragma unroll
            for (int q = 0; q < 2; q++) {
                x2p += dot4(rx[q], rx[q]);
                p2p += dot4(rp[q], rp[q]);
                a2p += dot4(ra[q], ra[q]);
                pap += dot4(rp[q], ra[q]);
                int k = (fk4 + q) * 4;
                Xs[(k + 0) * STR + frow] = rx[q].x;
                Xs[(k + 1) * STR + frow] = rx[q].y;
                Xs[(k + 2) * STR + frow] = rx[q].z;
                Xs[(k + 3) * STR + frow] = rx[q].w;
                Ps[(k + 0) * STR + frow] = rp[q].x;
                Ps[(k + 1) * STR + frow] = rp[q].y;
                Ps[(k + 2) * STR + frow] = rp[q].z;
                Ps[(k + 3) * STR + frow] = rp[q].w;
                As[(k + 0) * STR + frow] = ra[q].x;
                As[(k + 1) * STR + frow] = ra[q].y;
                As[(k + 2) * STR + frow] = ra[q].z;
                As[(k + 3) * STR + frow] = ra[q].w;
            }
            __syncthreads();             // tile ph+1 visible
        }
    }

    // ---- Stats reduction: 4 k-slab partials per row -> finals in smem.
    {
        const int slab = tid >> 6;
        sc_x2[slab * 64 + frow] = x2p;
        sc_p2[slab * 64 + frow] = p2p;
        sc_a2[slab * 64 + frow] = a2p;
        sc_pa[slab * 64 + frow] = pap;
    }
    __syncthreads();
    {
        const int r = tid & 63;
        if (tid < 64) {
            sx2[r] = sc_x2[r] + sc_x2[64 + r] + sc_x2[128 + r] + sc_x2[192 + r];
        } else if (tid < 128) {
            sp2[r] = sc_p2[r] + sc_p2[64 + r] + sc_p2[128 + r] + sc_p2[192 + r];
        } else if (tid < 192) {
            float a2 = sc_a2[r] + sc_a2[64 + r] + sc_a2[128 + r] + sc_a2[192 + r];
            float na = sqrtf(a2);
            sina[r] = fast_rcp(fmaxf(na, 1e-12f));
            sw2[r]  = 2.0f * na * LN2F;
        } else {
            spa[r] = sc_pa[r] + sc_pa[64 + r] + sc_pa[128 + r] + sc_pa[192 + r];
        }
    }
    __syncthreads();

    // ---- Epilogue: fused approx hyperbolic math, stats from smem.
    float x2v[4], x2p1[4];
    #pragma unroll
    for (int i = 0; i < 4; i++) {
        x2v[i]  = sx2[ty * 4 + i];
        x2p1[i] = 1.0f + x2v[i];
    }
    float p2v[4], bet[4], bet2[4], pav[4], inav[4], wv[4];
    #pragma unroll
    for (int j = 0; j < 4; j++) {
        p2v[j]  = sp2[tx * 4 + j];
        bet[j]  = 1.0f - p2v[j];
        bet2[j] = bet[j] * bet[j];
        pav[j]  = spa[tx * 4 + j];
        inav[j] = sina[tx * 4 + j];
        wv[j]   = sw2[tx * 4 + j];
    }

    #pragma unroll
    for (int i = 0; i < 4; i++) {
        const int n = n0 + ty * 4 + i;
        float res[4];
        #pragma unroll
        for (int j = 0; j < 4; j++) {
            float xp  = axp[i][j];                   // x.p
            float xa  = axa[i][j];                   // x.a
            float txy = -2.0f * xp;                  // 2*xy (xy = mp.x = -xp)
            float alpha = x2p1[i] + txy;             // 1 + 2xy + x2
            float den   = fmaf(p2v[j], x2v[i], 1.0f + txy);
            // s = ||res||^2 * den^2 = a^2 p2 + a*b*2xy + b^2 x2
            float s   = fmaf(alpha, fmaf(alpha, p2v[j], bet[j] * txy),
                             bet2[j] * x2v[i]);
            float num = fmaf(bet[j], xa, -alpha * pav[j]);   // b*xa - a*pa
            float d2ms = fmaf(den, den, -s);                 // den^2 - s
            // dot*lam = 2*den*num / (na * (den^2 - s))
            float arg = 2.0f * den * num * inav[j] * fast_rcp(d2ms);
            float q   = arg + fast_sqrt(fmaf(arg, arg, 1.0f));
            res[j] = wv[j] * fast_lg2(q);            // 2*na*ln2 * log2(q)
        }
        float4 o = {res[0], res[1], res[2], res[3]};
        *(float4*)&out[(size_t)n * C_TOT + c0 + tx * 4] = o;
    }
}

extern "C" void kernel_launch(void* const* d_in, const int* in_sizes, int n_in,
                              void* d_out, int out_size) {
    const float* X = (const float*)d_in[0];   // output_before (N, D)
    const float* A = (const float*)d_in[1];   // a_mlr (C, D)
    const float* P = (const float*)d_in[2];   // p_mlr (C, D)
    float* out = (float*)d_out;               // (N, C)

    cudaFuncSetAttribute(hyp_mlr_kernel,
                         cudaFuncAttributeMaxDynamicSharedMemorySize,
                         SMEM_BYTES);

    dim3 grid(C_TOT / BC, N_TOT / BN);        // (4, 64) = 256 blocks
    hyp_mlr_kernel<<<grid, 256, SMEM_BYTES>>>(X, A, P, out);
}